// round 9
// baseline (speedup 1.0000x reference)
#include <cuda_runtime.h>
#include <math.h>

// ---------------------------------------------------------------------------
// EncoderGRUODE: B=256, T=512, D_IN=64, H=128
// 128 CTAs x 256 threads. Thread (half = lane>>4, i = 16*warp + (lane&15)):
// owns element i of row `half`, computes k-half `half` of every dot.
// Half-exchange via shfl_xor(16). All dots use fma.rn.f32x2 (FFMA2).
// W_node in regs; W_hh R,Z in SMEM; W_hh N / W_ih / W_out streamed from L2.
// ---------------------------------------------------------------------------

#define B_   256
#define T_   512
#define DIN  64
#define H_   128

typedef unsigned long long ull;

// packed weights produced by prep_kernel (all k-major, i/j-contiguous)
__device__ float4 g_whh4[12288];   // [0:4096) R | [4096:8192) Z | [8192:12288) N ; idx=(k/4)*128+i
__device__ float4 g_wih4[6144];    // gate g*2048 + (k/4)*128 + i -> {W_ih[g*128+i][k..k+3]}
__device__ float4 g_wout4[2048];   // (k/4)*64 + j -> {W_out[j][k..k+3]}
__device__ int    g_mask[T_];
__device__ float  g_dt[T_];

// ---------------------------------------------------------------------------
__global__ void prep_kernel(const float* __restrict__ W_hh,
                            const float* __restrict__ W_ih,
                            const float* __restrict__ W_out,
                            const unsigned char* __restrict__ mask_raw,
                            const float* __restrict__ tp)
{
    int gtid = blockIdx.x * blockDim.x + threadIdx.x;
    int nthr = gridDim.x * blockDim.x;

    for (int idx = gtid; idx < 4096; idx += nthr) {
        int kq = idx >> 7, i = idx & 127, k = kq * 4;
        g_whh4[idx] = make_float4(W_hh[i * H_ + k],     W_hh[i * H_ + k + 1],
                                  W_hh[i * H_ + k + 2], W_hh[i * H_ + k + 3]);
        int iz = H_ + i;
        g_whh4[4096 + idx] = make_float4(W_hh[iz * H_ + k],     W_hh[iz * H_ + k + 1],
                                         W_hh[iz * H_ + k + 2], W_hh[iz * H_ + k + 3]);
        int in_ = 2 * H_ + i;
        g_whh4[8192 + idx] = make_float4(W_hh[in_ * H_ + k],     W_hh[in_ * H_ + k + 1],
                                         W_hh[in_ * H_ + k + 2], W_hh[in_ * H_ + k + 3]);
    }
    for (int idx = gtid; idx < 6144; idx += nthr) {
        int g = idx >> 11;
        int rem = idx & 2047;
        int kq = rem >> 7, i = rem & 127, k = kq * 4;
        int row = g * H_ + i;
        g_wih4[idx] = make_float4(W_ih[row * DIN + k],     W_ih[row * DIN + k + 1],
                                  W_ih[row * DIN + k + 2], W_ih[row * DIN + k + 3]);
    }
    for (int idx = gtid; idx < 2048; idx += nthr) {
        int kq = idx >> 6, j = idx & 63, k = kq * 4;
        g_wout4[idx] = make_float4(W_out[j * H_ + k],     W_out[j * H_ + k + 1],
                                   W_out[j * H_ + k + 2], W_out[j * H_ + k + 3]);
    }
    if (gtid < T_)
        g_dt[gtid] = (gtid == 0) ? 0.01f : (tp[gtid] - tp[gtid - 1]);

    // robust mask decode (uint8 / int32 / float32) — unchanged (passed R5-R8)
    if (blockIdx.x == 0 && threadIdx.x == 0) {
        bool nz_nonmult = false, one_mult = false, f32_sig = true;
        for (int i = 0; i < T_; i++) {
            unsigned char v = mask_raw[i];
            int m4 = i & 3;
            if (m4 != 0 && v) nz_nonmult = true;
            if (m4 == 0 && v == 1) one_mult = true;
            if (m4 == 0 || m4 == 1) { if (v != 0) f32_sig = false; }
            else if (m4 == 2)       { if (v != 0 && v != 0x80) f32_sig = false; }
            else                    { if (v != 0 && v != 0x3F) f32_sig = false; }
        }
        if (!nz_nonmult && one_mult) {
            const int* mi = (const int*)mask_raw;
            for (int i = 0; i < T_; i++) g_mask[i] = (mi[i] != 0);
        } else if (nz_nonmult && f32_sig) {
            const float* mf = (const float*)mask_raw;
            for (int i = 0; i < T_; i++) g_mask[i] = (mf[i] != 0.0f);
        } else {
            for (int i = 0; i < T_; i++) g_mask[i] = (mask_raw[i] != 0);
        }
    }
}

// ---------------------------------------------------------------------------
// SMEM layout (float offsets). Only W_hh R,Z live in SMEM now (128 KB).
#define RS       132
#define SMF_WHH  0        // 32768 floats: R [0:16384) | Z [16384:32768) as float4 idx=(k/4)*128+i
#define SMF_A    32768    // 264: h      [row*RS + k]
#define SMF_B    33032    // 264: RK4 scratch
#define SMF_C    33296    // 264: RK4 scratch
#define SMF_HO   33560    // 264: h_ode
#define SMF_INP  33824    // 136: inp [row*68 + j]
#define SMF_PO   33960    // 128: prev_out [row*64 + j]
#define SMF_XO   34088    // 512: out-proj partials [row*256 + kq*64 + j]
#define SMF_DT   34600    // 512
#define SMF_MSK  35112    // 512 (ints)
#define SMF_TOT  35624
#define SMEM_BYTES (SMF_TOT * 4)   // 142496 B

__device__ __forceinline__ void fma2(ull& acc, ull a, ull b) {
    asm("fma.rn.f32x2 %0, %1, %2, %0;" : "+l"(acc) : "l"(a), "l"(b));
}
__device__ __forceinline__ float psum(ull a) {
    float2 f = *reinterpret_cast<float2*>(&a);
    return f.x + f.y;
}
__device__ __forceinline__ float tanh_fast(float x) {
    float y;
    asm("tanh.approx.f32 %0, %1;" : "=f"(y) : "f"(x));
    return y;
}
__device__ __forceinline__ float sig_fast(float x) {
    return fmaf(0.5f, tanh_fast(0.5f * x), 0.5f);
}

__global__ void __launch_bounds__(256, 1)
enc_gruode_kernel(const float* __restrict__ x,
                  const float* __restrict__ b_ih,
                  const float* __restrict__ b_hh,
                  const float* __restrict__ W_node,
                  const float* __restrict__ b_node,
                  const float* __restrict__ b_out,
                  float* __restrict__ out)
{
    extern __shared__ float sm[];
    int* smi = (int*)sm;
    const int tid  = threadIdx.x;
    const int lane = tid & 31;
    const int wrp  = tid >> 5;
    const int half = lane >> 4;                 // k-half AND my row
    const int i    = (wrp << 4) | (lane & 15);  // my element

    // ---- stage W_hh R,Z into SMEM ----
    {
        float4* d = (float4*)sm;
        for (int idx = tid; idx < 8192; idx += 256) d[idx] = g_whh4[idx];
    }
    for (int idx = tid; idx < 512; idx += 256) {
        sm[SMF_DT + idx]   = g_dt[idx];
        smi[SMF_MSK + idx] = g_mask[idx];
    }
    for (int idx = tid; idx < 264; idx += 256) sm[SMF_A + idx] = 0.0f;
    if (tid < 128) sm[SMF_PO + tid] = b_out[tid & 63];   // prev_out at t=0 (h0=0)

    // ---- register weights: only W_node half-row (64 floats = 32 ull) ----
    ull wn2[32];
    {
        const ulonglong2* ws = (const ulonglong2*)(W_node + (size_t)i * H_ + 64 * half);
#pragma unroll
        for (int q = 0; q < 16; q++) { ulonglong2 v = ws[q]; wn2[2*q] = v.x; wn2[2*q+1] = v.y; }
    }

    // combiner constants
    const float bn_i = b_node[i];
    const float bs_r = b_ih[i]       + b_hh[i];
    const float bs_z = b_ih[128 + i] + b_hh[128 + i];
    const float bihn = b_ih[256 + i];
    const float bhhn = b_hh[256 + i];
    const float bo   = (tid < 128) ? b_out[tid & 63] : 0.0f;

    // x / out pointers for the tid<128 role (row = tid>>6, j = tid&63)
    const float* xr   = x   + (size_t)(2 * blockIdx.x + (tid >> 6)) * T_ * DIN + (tid & 63);
    float*       orow = out + (size_t)(2 * blockIdx.x + (tid >> 6)) * T_ * DIN + (tid & 63);

    __syncthreads();

    float hreg = 0.0f;
    float xv = (tid < 128) ? __ldg(xr) : 0.0f;   // prefetch x[t=0]

    // one RK4 matvec: full dot for my row via half-dot + shfl_xor(16)
    auto STAGE = [&](const float* buf) -> float {
        const ulonglong2* U = (const ulonglong2*)(buf + 64 * half);
        const ulonglong2* V = (const ulonglong2*)(buf + RS + 64 * half);
        ull a0 = 0, a1 = 0, c0 = 0, c1 = 0;
#pragma unroll
        for (int q = 0; q < 16; q++) {
            ulonglong2 u = U[q], v = V[q];
            fma2(a0, wn2[2*q], u.x); fma2(a1, wn2[2*q+1], u.y);
            fma2(c0, wn2[2*q], v.x); fma2(c1, wn2[2*q+1], v.y);
        }
        float p0 = psum(a0) + psum(a1);          // row0 partial, my k-half
        float p1 = psum(c0) + psum(c1);          // row1 partial
        float mine = half ? p1 : p0;
        float oth  = __shfl_xor_sync(0xffffffffu, half ? p0 : p1, 16);
        return mine + oth + bn_i;
    };

    const ulonglong2* WIHg = (const ulonglong2*)g_wih4;   // L2-resident
    const ulonglong2* WNg  = (const ulonglong2*)g_whh4 + 8192;
    const ulonglong2* WOg  = (const ulonglong2*)g_wout4;
    const ulonglong2* W2   = (const ulonglong2*)sm;       // R at 0, Z at +4096

    for (int t = 0; t < T_; ++t) {
        const float dt  = sm[SMF_DT + t];
        const int   msk = smi[SMF_MSK + t];
        const float hdt = 0.5f * dt;

        // ---- RK4 stage 1: read A -> write B ----
        float kv = tanh_fast(STAGE(sm + SMF_A));
        float ksum = kv;
        sm[SMF_B + half * RS + i] = fmaf(hdt, kv, hreg);
        __syncthreads();                                             // B1

        // input staging (PO ordered by B1); prefetch next x
        if (tid < 128) {
            sm[SMF_INP + (tid >> 6) * 68 + (tid & 63)] = msk ? xv : sm[SMF_PO + tid];
            if (t + 1 < T_) xv = __ldg(xr + (size_t)(t + 1) * DIN);
        }

        // ---- RK4 stage 2: read B -> write C ----
        kv = tanh_fast(STAGE(sm + SMF_B));
        ksum = fmaf(2.0f, kv, ksum);
        sm[SMF_C + half * RS + i] = fmaf(hdt, kv, hreg);
        __syncthreads();                                             // B2

        // ---- i-gate partials (W_ih streamed from L2), kept in regs ----
        float irT, izT, inT;
        {
            const ulonglong2* IU = (const ulonglong2*)(sm + SMF_INP + 32 * half);
            const ulonglong2* IV = (const ulonglong2*)(sm + SMF_INP + 68 + 32 * half);
            ull ar = 0, az = 0, an = 0, br = 0, bz = 0, bn2 = 0;
#pragma unroll
            for (int q = 0; q < 8; q++) {
                const int widx = (8 * half + q) * 128 + i;
                ulonglong2 wr = WIHg[widx];
                ulonglong2 wz = WIHg[2048 + widx];
                ulonglong2 wn = WIHg[4096 + widx];
                ulonglong2 u = IU[q], v = IV[q];
                fma2(ar, wr.x, u.x); fma2(ar, wr.y, u.y);
                fma2(az, wz.x, u.x); fma2(az, wz.y, u.y);
                fma2(an, wn.x, u.x); fma2(an, wn.y, u.y);
                fma2(br, wr.x, v.x); fma2(br, wr.y, v.y);
                fma2(bz, wz.x, v.x); fma2(bz, wz.y, v.y);
                fma2(bn2, wn.x, v.x); fma2(bn2, wn.y, v.y);
            }
            float r0 = psum(ar), r1 = psum(br);
            float z0 = psum(az), z1 = psum(bz);
            float n0 = psum(an), n1 = psum(bn2);
            irT = (half ? r1 : r0) + __shfl_xor_sync(0xffffffffu, half ? r0 : r1, 16);
            izT = (half ? z1 : z0) + __shfl_xor_sync(0xffffffffu, half ? z0 : z1, 16);
            inT = (half ? n1 : n0) + __shfl_xor_sync(0xffffffffu, half ? n0 : n1, 16);
        }

        // ---- RK4 stage 3: read C -> write B ----
        kv = tanh_fast(STAGE(sm + SMF_C));
        ksum = fmaf(2.0f, kv, ksum);
        sm[SMF_B + half * RS + i] = fmaf(dt, kv, hreg);
        __syncthreads();                                             // B3

        // ---- RK4 stage 4: read B -> h_ode ----
        kv = tanh_fast(STAGE(sm + SMF_B));
        const float hode = fmaf(dt * (1.0f / 6.0f), ksum + kv, hreg);
        sm[SMF_HO + half * RS + i] = hode;
        __syncthreads();                                             // B4

        // ---- GRU W_hh partials (R,Z from SMEM; N from L2) + gate combine ----
        {
            const ulonglong2* HU = (const ulonglong2*)(sm + SMF_HO + 64 * half);
            const ulonglong2* HV = (const ulonglong2*)(sm + SMF_HO + RS + 64 * half);
            ull R0 = 0, R1 = 0, Z0 = 0, Z1 = 0, N0 = 0, N1 = 0;
#pragma unroll
            for (int q = 0; q < 16; q++) {
                const int idx = (16 * half + q) * 128 + i;
                ulonglong2 wr = W2[idx];
                ulonglong2 wz = W2[4096 + idx];
                ulonglong2 wn = WNg[idx];
                ulonglong2 u = HU[q], v = HV[q];
                fma2(R0, wr.x, u.x); fma2(R0, wr.y, u.y);
                fma2(R1, wr.x, v.x); fma2(R1, wr.y, v.y);
                fma2(Z0, wz.x, u.x); fma2(Z0, wz.y, u.y);
                fma2(Z1, wz.x, v.x); fma2(Z1, wz.y, v.y);
                fma2(N0, wn.x, u.x); fma2(N0, wn.y, u.y);
                fma2(N1, wn.x, v.x); fma2(N1, wn.y, v.y);
            }
            float r0 = psum(R0), r1 = psum(R1);
            float z0 = psum(Z0), z1 = psum(Z1);
            float n0 = psum(N0), n1 = psum(N1);
            float hrT = (half ? r1 : r0) + __shfl_xor_sync(0xffffffffu, half ? r0 : r1, 16);
            float hzT = (half ? z1 : z0) + __shfl_xor_sync(0xffffffffu, half ? z0 : z1, 16);
            float hnT = (half ? n1 : n0) + __shfl_xor_sync(0xffffffffu, half ? n0 : n1, 16);

            float rr = sig_fast(irT + hrT + bs_r);
            float zz = sig_fast(izT + hzT + bs_z);
            float nn = tanh_fast(inT + bihn + rr * (hnT + bhhn));
            hreg = nn + zz * (hode - nn);
            sm[SMF_A + half * RS + i] = hreg;
        }
        __syncthreads();                                             // B5

        // ---- output projection partials: j = i&63, k-quarter kq, BOTH rows ----
        {
            const int j = i & 63, kq = (i >> 6) | (half << 1);
            const ulonglong2* S0 = (const ulonglong2*)(sm + SMF_A + 32 * kq);
            const ulonglong2* S1 = (const ulonglong2*)(sm + SMF_A + RS + 32 * kq);
            ull o0 = 0, o1 = 0;
#pragma unroll
            for (int q = 0; q < 8; q++) {
                ulonglong2 w = WOg[(size_t)(8 * kq + q) * 64 + j];
                ulonglong2 s0 = S0[q], s1 = S1[q];
                fma2(o0, w.x, s0.x); fma2(o0, w.y, s0.y);
                fma2(o1, w.x, s1.x); fma2(o1, w.y, s1.y);
            }
            sm[SMF_XO + kq * 64 + j]       = psum(o0);
            sm[SMF_XO + 256 + kq * 64 + j] = psum(o1);
        }
        __syncthreads();                                             // B6

        // ---- output combine (also next step's prev_out); next B1 orders PO.
        if (tid < 128) {
            const int base = SMF_XO + (tid >> 6) * 256 + (tid & 63);
            float y = sm[base] + sm[base + 64] + sm[base + 128] + sm[base + 192] + bo;
            orow[(size_t)t * DIN] = y;
            sm[SMF_PO + tid] = y;
        }
    }
}

// ---------------------------------------------------------------------------
extern "C" void kernel_launch(void* const* d_in, const int* in_sizes, int n_in,
                              void* d_out, int out_size)
{
    const float*         x      = (const float*)d_in[0];
    const float*         tp     = (const float*)d_in[1];
    const unsigned char* mask   = (const unsigned char*)d_in[2];
    const float*         W_ih   = (const float*)d_in[3];
    const float*         W_hh   = (const float*)d_in[4];
    const float*         b_ih   = (const float*)d_in[5];
    const float*         b_hh   = (const float*)d_in[6];
    const float*         W_node = (const float*)d_in[7];
    const float*         b_node = (const float*)d_in[8];
    const float*         W_out  = (const float*)d_in[9];
    const float*         b_out  = (const float*)d_in[10];
    float*               out    = (float*)d_out;

    prep_kernel<<<32, 256>>>(W_hh, W_ih, W_out, mask, tp);

    cudaFuncSetAttribute(enc_gruode_kernel,
                         cudaFuncAttributeMaxDynamicSharedMemorySize,
                         SMEM_BYTES);
    enc_gruode_kernel<<<B_ / 2, 256, SMEM_BYTES>>>(
        x, b_ih, b_hh, W_node, b_node, b_out, out);
}